// round 12
// baseline (speedup 1.0000x reference)
#include <cuda_runtime.h>
#include <cuda_bf16.h>
#include <math.h>
#include <stdint.h>

// Problem constants
#define BDIM   8
#define LLEAF  16384
#define NNODE  32767      // 2*L - 1
#define DH     256
#define MAXN   16384
#define XELEMS 67106816ULL   // 8*32767*256

// ---------------------------------------------------------------------------
// Static device scratch
// ---------------------------------------------------------------------------
// pre: interleaved gates, rows indexed by gm = b*NNODE + node (internal only)
__device__ float g_pre[268427264];          // 8*32767*1024
__device__ float g_c[2][33554432];          // ping-pong c (fp32)
__device__ __nv_bfloat16 g_hhi[2][33554432], g_hlo[2][33554432];  // split h
__device__ __nv_bfloat16 g_xhi[67106816], g_xlo[67106816];        // split x

// Packed transposed INTERLEAVED weights: row n=4j+t -> (t<3 ? Wiou[:,t*256+j] : Wf[:,j])
__device__ __nv_bfloat16 g_wcat_hi[262144], g_wcat_lo[262144];
__device__ __nv_bfloat16 g_ucat_hi[262144], g_ucat_lo[262144];
__device__ float g_bias[1024];

__device__ __forceinline__ float sigm(float v) { return 1.0f / (1.0f + expf(-v)); }

__device__ __forceinline__ uint32_t smem_u32(const void* p) {
    uint32_t a;
    asm("{ .reg .u64 t; cvta.to.shared.u64 t, %1; cvt.u32.u64 %0, t; }" : "=r"(a) : "l"(p));
    return a;
}

#define LDSM_X4(r0, r1, r2, r3, addr) \
    asm volatile("ldmatrix.sync.aligned.m8n8.x4.shared.b16 {%0,%1,%2,%3}, [%4];" \
                 : "=r"(r0), "=r"(r1), "=r"(r2), "=r"(r3) : "r"(addr))
#define LDSM_X2(r0, r1, addr) \
    asm volatile("ldmatrix.sync.aligned.m8n8.x2.shared.b16 {%0,%1}, [%2];" \
                 : "=r"(r0), "=r"(r1) : "r"(addr))
#define MMA_BF16(d, a0, a1, a2, a3, b0, b1) \
    asm volatile("mma.sync.aligned.m16n8k16.row.col.f32.bf16.bf16.f32 " \
                 "{%0,%1,%2,%3}, {%4,%5,%6,%7}, {%8,%9}, {%0,%1,%2,%3};" \
                 : "+f"((d)[0]), "+f"((d)[1]), "+f"((d)[2]), "+f"((d)[3]) \
                 : "r"(a0), "r"(a1), "r"(a2), "r"(a3), "r"(b0), "r"(b1))
#define CP_ASYNC(dst, src, sz) \
    asm volatile("cp.async.cg.shared.global [%0], [%1], 16, %2;" \
                 :: "r"(dst), "l"(src), "r"(sz))
#define CP_COMMIT() asm volatile("cp.async.commit_group;")
#define CP_WAIT1()  asm volatile("cp.async.wait_group 1;")
#define CP_WAIT0()  asm volatile("cp.async.wait_group 0;")

// ---------------------------------------------------------------------------
// Weight prep: pack interleaved-transposed [i_j,o_j,u_j,f_j] weights, hi/lo.
// ---------------------------------------------------------------------------
__global__ void prep_kernel(const float* __restrict__ W_iou,
                            const float* __restrict__ b_iou,
                            const float* __restrict__ U_iou,
                            const float* __restrict__ W_f,
                            const float* __restrict__ b_f,
                            const float* __restrict__ U_f) {
    int gid = blockIdx.x * blockDim.x + threadIdx.x;   // < 524288
    if (gid < 1024) {
        int j = gid >> 2, t = gid & 3;
        g_bias[gid] = (t < 3) ? b_iou[t * 256 + j] : b_f[j];
    }
    float v; __nv_bfloat16 *phi, *plo; int oi;
    if (gid < 262144) {            // Wcat^T
        int nn = gid >> 8, k = gid & 255;
        int j = nn >> 2, t = nn & 3;
        v = (t < 3) ? W_iou[k * 768 + t * 256 + j] : W_f[k * 256 + j];
        phi = g_wcat_hi; plo = g_wcat_lo; oi = gid;
    } else {                       // Ucat^T
        int tt = gid - 262144; int nn = tt >> 8, k = tt & 255;
        int j = nn >> 2, t = nn & 3;
        v = (t < 3) ? U_iou[k * 768 + t * 256 + j] : U_f[k * 256 + j];
        phi = g_ucat_hi; plo = g_ucat_lo; oi = tt;
    }
    __nv_bfloat16 hi = __float2bfloat16_rn(v);
    phi[oi] = hi;
    plo[oi] = __float2bfloat16_rn(v - __bfloat162float(hi));
}

// ---------------------------------------------------------------------------
// Split x (fp32) into bf16 hi/lo arrays.
// ---------------------------------------------------------------------------
__global__ void split_x_kernel(const float* __restrict__ x) {
    size_t base = ((size_t)blockIdx.x * 256 + threadIdx.x) * 4;
    if (base >= XELEMS) return;
    float4 v = *(const float4*)(x + base);
    __nv_bfloat162 h0 = __floats2bfloat162_rn(v.x, v.y);
    __nv_bfloat162 h1 = __floats2bfloat162_rn(v.z, v.w);
    __nv_bfloat162 l0 = __floats2bfloat162_rn(
        v.x - __bfloat162float(__low2bfloat16(h0)),
        v.y - __bfloat162float(__high2bfloat16(h0)));
    __nv_bfloat162 l1 = __floats2bfloat162_rn(
        v.z - __bfloat162float(__low2bfloat16(h1)),
        v.w - __bfloat162float(__high2bfloat16(h1)));
    *(uint2*)(g_xhi + base) = make_uint2(*(uint32_t*)&h0, *(uint32_t*)&h1);
    *(uint2*)(g_xlo + base) = make_uint2(*(uint32_t*)&l0, *(uint32_t*)&l1);
}

// ---------------------------------------------------------------------------
// Fused HMMA bf16x3 GEMM, cp.async double-buffered, gate-fused epilogues.
//   mode 0: C = x @ Wcat + bias ; internal rows -> g_pre, leaf rows -> leaf
//           activation written to h/c[pout].
//   mode 1: per-child projections h_child @ Ucat, fused with combine:
//           sibling+partner shuffles -> parent gates -> h/c[pout].
//   A row map: lgn<0 -> row=gm ; else b=gm>>lgn, kk=gm&(2^lgn-1), row=b*MAXN+kk
// ---------------------------------------------------------------------------
#define ARR_B   (128 * 144)
#define OFF_AHI 0
#define OFF_ALO ARR_B
#define OFF_BHI (2 * ARR_B)
#define OFF_BLO (3 * ARR_B)
#define STAGE_B (4 * ARR_B)          // 73728
#define SMEM_TOTAL (2 * STAGE_B)     // 147456

struct LoadCtx {
    const __nv_bfloat16 *sAhi[4], *sAlo[4], *sBhi[4], *sBlo[4];
    uint32_t szA[4], doff[4];
};

__device__ __forceinline__ void issue_stage(const LoadCtx& L, uint32_t sbase, int chunk) {
#pragma unroll
    for (int p = 0; p < 4; p++) {
        CP_ASYNC(sbase + OFF_AHI + L.doff[p], L.sAhi[p] + chunk * 64, L.szA[p]);
        CP_ASYNC(sbase + OFF_ALO + L.doff[p], L.sAlo[p] + chunk * 64, L.szA[p]);
        CP_ASYNC(sbase + OFF_BHI + L.doff[p], L.sBhi[p] + chunk * 64, 16u);
        CP_ASYNC(sbase + OFF_BLO + L.doff[p], L.sBlo[p] + chunk * 64, 16u);
    }
    CP_COMMIT();
}

__global__ __launch_bounds__(256, 1)
void gemm_fused(const __nv_bfloat16* __restrict__ Ahi,
                const __nv_bfloat16* __restrict__ Alo,
                const __nv_bfloat16* __restrict__ Bhi,
                const __nv_bfloat16* __restrict__ Blo,
                int M, int lgn, int mode, int n, int pin, int pout) {
    extern __shared__ char smem[];
    const uint32_t sb = smem_u32(smem);
    const int tid = threadIdx.x;
    const int wid = tid >> 5, lid = tid & 31;
    const int wm = wid >> 2, wn = wid & 3;
    const int m0 = blockIdx.y * 128;
    const int n0 = blockIdx.x * 128;

    float acc[4][4][4];
#pragma unroll
    for (int mi = 0; mi < 4; mi++)
#pragma unroll
        for (int ni = 0; ni < 4; ni++)
#pragma unroll
            for (int q = 0; q < 4; q++) acc[mi][ni][q] = 0.0f;

    // ---- loader context ----
    LoadCtx L;
    {
        const int rs = tid >> 3;
        const int seg = tid & 7;
#pragma unroll
        for (int p = 0; p < 4; p++) {
            int r = rs + 32 * p;
            L.doff[p] = (uint32_t)(r * 144 + seg * 16);
            int gm = m0 + r;
            size_t row = 0;
            if (gm < M) {
                if (lgn < 0) row = (size_t)gm;
                else {
                    int b = gm >> lgn;
                    int kk = gm & ((1 << lgn) - 1);
                    row = (size_t)b * MAXN + kk;
                }
                L.szA[p] = 16;
            } else L.szA[p] = 0;
            L.sAhi[p] = Ahi + row * 256 + seg * 8;
            L.sAlo[p] = Alo + row * 256 + seg * 8;
            int nn = n0 + r;
            L.sBhi[p] = Bhi + (size_t)nn * 256 + seg * 8;
            L.sBlo[p] = Blo + (size_t)nn * 256 + seg * 8;
        }
    }

    const int arow = lid & 15, ahalf = lid >> 4;
    const int brow = lid & 7,  bhalf = (lid >> 3) & 1;

    issue_stage(L, sb, 0);
    issue_stage(L, sb + STAGE_B, 1);

#pragma unroll
    for (int c = 0; c < 4; c++) {
        if (c < 3) CP_WAIT1(); else CP_WAIT0();
        __syncthreads();
        const uint32_t sbase = sb + (uint32_t)(c & 1) * STAGE_B;

#pragma unroll
        for (int ks = 0; ks < 4; ks++) {
            uint32_t bh[4][2], bl[4][2];
#pragma unroll
            for (int ni = 0; ni < 4; ni++) {
                uint32_t ba = sbase + (uint32_t)((wn * 32 + ni * 8 + brow) * 144
                                                 + ks * 32 + bhalf * 16);
                LDSM_X2(bh[ni][0], bh[ni][1], ba + OFF_BHI);
                LDSM_X2(bl[ni][0], bl[ni][1], ba + OFF_BLO);
            }
#pragma unroll
            for (int mi = 0; mi < 4; mi++) {
                uint32_t aa = sbase + (uint32_t)((wm * 64 + mi * 16 + arow) * 144
                                                 + ks * 32 + ahalf * 16);
                uint32_t ah0, ah1, ah2, ah3, al0, al1, al2, al3;
                LDSM_X4(ah0, ah1, ah2, ah3, aa + OFF_AHI);
                LDSM_X4(al0, al1, al2, al3, aa + OFF_ALO);
#pragma unroll
                for (int ni = 0; ni < 4; ni++) {
                    MMA_BF16(acc[mi][ni], ah0, ah1, ah2, ah3, bh[ni][0], bh[ni][1]);
                    MMA_BF16(acc[mi][ni], ah0, ah1, ah2, ah3, bl[ni][0], bl[ni][1]);
                    MMA_BF16(acc[mi][ni], al0, al1, al2, al3, bh[ni][0], bh[ni][1]);
                }
            }
        }
        __syncthreads();
        if (c < 2) issue_stage(L, sbase, c + 2);
    }

    // ======================= fused epilogues =======================
    const int crow = lid >> 2;          // 0..7

    if (mode == 0) {
        // pre-write for internal nodes, leaf activation for leaf rows
#pragma unroll
        for (int mi = 0; mi < 4; mi++) {
            int gmr[2];  gmr[0] = m0 + wm * 64 + mi * 16 + crow; gmr[1] = gmr[0] + 8;
            int isLeaf[2]; size_t leafB[2];
#pragma unroll
            for (int h = 0; h < 2; h++) {
                int gm = gmr[h];
                int b = gm / NNODE;
                int node = gm - b * NNODE;
                isLeaf[h] = (node >= LLEAF - 1);
                leafB[h] = ((size_t)b * MAXN + (node - (LLEAF - 1))) * 256;
            }
#pragma unroll
            for (int ni = 0; ni < 4; ni++) {
                const int gc = n0 + wn * 32 + ni * 8 + (lid & 3) * 2;
                float b0 = g_bias[gc], b1 = g_bias[gc + 1];
                float v0 = acc[mi][ni][0] + b0, v1 = acc[mi][ni][1] + b1;
                float v2 = acc[mi][ni][2] + b0, v3 = acc[mi][ni][3] + b1;
                // partner lane holds (u,f) for this j
                float u0 = __shfl_xor_sync(0xffffffffu, v0, 1);
                float u1 = __shfl_xor_sync(0xffffffffu, v2, 1);
#pragma unroll
                for (int h = 0; h < 2; h++) {
                    int gm = gmr[h];
                    if (gm >= M) continue;
                    float iV = h ? v2 : v0, oV = h ? v3 : v1, uV = h ? u1 : u0;
                    if (isLeaf[h]) {
                        if ((lid & 1) == 0) {
                            float cv = sigm(iV) * tanhf(uV);
                            float hv = sigm(oV) * tanhf(cv);
                            size_t o = leafB[h] + (gc >> 2);
                            g_c[pout][o] = cv;
                            __nv_bfloat16 hh = __float2bfloat16_rn(hv);
                            g_hhi[pout][o] = hh;
                            g_hlo[pout][o] = __float2bfloat16_rn(hv - __bfloat162float(hh));
                        }
                    } else {
                        float2 w = h ? make_float2(v2, v3) : make_float2(v0, v1);
                        *(float2*)(g_pre + (size_t)gm * 1024 + gc) = w;
                    }
                }
            }
        }
    } else {
        // combine fusion: rows are children; sibling pairs at crow, crow^1
#pragma unroll
        for (int mi = 0; mi < 4; mi++) {
            int gmr[2];  gmr[0] = m0 + wm * 64 + mi * 16 + crow; gmr[1] = gmr[0] + 8;
            size_t preB[2], outB[2], childB[2];
#pragma unroll
            for (int h = 0; h < 2; h++) {
                int gm = gmr[h];
                int b = gm >> lgn;
                int kk = gm & ((1 << lgn) - 1);
                preB[h]   = ((size_t)b * NNODE + (n - 1) + (kk >> 1)) * 1024;
                outB[h]   = ((size_t)b * MAXN + (kk >> 1)) * 256;
                childB[h] = ((size_t)b * MAXN + kk) * 256;
            }
#pragma unroll
            for (int ni = 0; ni < 4; ni++) {
                const int gc = n0 + wn * 32 + ni * 8 + (lid & 3) * 2;
                const int j = gc >> 2;
                float v0 = acc[mi][ni][0], v1 = acc[mi][ni][1];
                float v2 = acc[mi][ni][2], v3 = acc[mi][ni][3];
                // sibling child row (crow ^ 1) -> xor 4 on lane id
                float s0 = __shfl_xor_sync(0xffffffffu, v0, 4);
                float s1 = __shfl_xor_sync(0xffffffffu, v1, 4);
                float s2 = __shfl_xor_sync(0xffffffffu, v2, 4);
                float s3 = __shfl_xor_sync(0xffffffffu, v3, 4);
                // partner lane (t-pair) -> xor 1 : u,f of both children
                float uv0 = __shfl_xor_sync(0xffffffffu, v0, 1);
                float fv1 = __shfl_xor_sync(0xffffffffu, v1, 1);
                float uv2 = __shfl_xor_sync(0xffffffffu, v2, 1);
                float fv3 = __shfl_xor_sync(0xffffffffu, v3, 1);
                float us0 = __shfl_xor_sync(0xffffffffu, s0, 1);
                float fs1 = __shfl_xor_sync(0xffffffffu, s1, 1);
                float us2 = __shfl_xor_sync(0xffffffffu, s2, 1);
                float fs3 = __shfl_xor_sync(0xffffffffu, s3, 1);
                if ((lid & 5) == 0) {
#pragma unroll
                    for (int h = 0; h < 2; h++) {
                        int gm = gmr[h];
                        if (gm >= M) continue;
                        float i0 = h ? v2 : v0,  o0 = h ? v3 : v1;
                        float u0 = h ? uv2 : uv0, f0g = h ? fv3 : fv1;
                        float i1 = h ? s2 : s0,  o1 = h ? s3 : s1;
                        float u1 = h ? us2 : us0, f1g = h ? fs3 : fs1;
                        float4 p4 = *(const float4*)(g_pre + preB[h] + 4 * j);
                        float iv = p4.x + i0 + i1;
                        float ov = p4.y + o0 + o1;
                        float uv = p4.z + u0 + u1;
                        float f0 = sigm(p4.w + f0g);
                        float f1 = sigm(p4.w + f1g);
                        float c0 = g_c[pin][childB[h] + j];
                        float c1 = g_c[pin][childB[h] + 256 + j];
                        float cn = sigm(iv) * tanhf(uv) + f0 * c0 + f1 * c1;
                        float hn = sigm(ov) * tanhf(cn);
                        size_t o = outB[h] + j;
                        g_c[pout][o] = cn;
                        __nv_bfloat16 hh = __float2bfloat16_rn(hn);
                        g_hhi[pout][o] = hh;
                        g_hlo[pout][o] = __float2bfloat16_rn(hn - __bfloat162float(hh));
                    }
                }
            }
        }
    }
}

// ---------------------------------------------------------------------------
__global__ void final_kernel(int p, float* __restrict__ out) {
    int gid = blockIdx.x * blockDim.x + threadIdx.x;
    if (gid >= BDIM * 512) return;
    int b = gid >> 9;
    int j = gid & 511;
    size_t base = ((size_t)b * MAXN) * 256;
    if (j < 256) {
        out[gid] = __bfloat162float(g_hhi[p][base + j])
                 + __bfloat162float(g_hlo[p][base + j]);
    } else {
        out[gid] = g_c[p][base + j - 256];
    }
}

// ---------------------------------------------------------------------------
extern "C" void kernel_launch(void* const* d_in, const int* in_sizes, int n_in,
                              void* d_out, int out_size) {
    const float* x     = (const float*)d_in[0];
    const float* W_iou = (const float*)d_in[1];
    const float* b_iou = (const float*)d_in[2];
    const float* U_iou = (const float*)d_in[3];
    const float* W_f   = (const float*)d_in[4];
    const float* b_f   = (const float*)d_in[5];
    const float* U_f   = (const float*)d_in[6];
    float* out = (float*)d_out;

    __nv_bfloat16 *pXhi, *pXlo, *pHhi, *pHlo, *pWH, *pWL, *pUH, *pUL;
    cudaGetSymbolAddress((void**)&pXhi, g_xhi);
    cudaGetSymbolAddress((void**)&pXlo, g_xlo);
    cudaGetSymbolAddress((void**)&pHhi, g_hhi);
    cudaGetSymbolAddress((void**)&pHlo, g_hlo);
    cudaGetSymbolAddress((void**)&pWH, g_wcat_hi);
    cudaGetSymbolAddress((void**)&pWL, g_wcat_lo);
    cudaGetSymbolAddress((void**)&pUH, g_ucat_hi);
    cudaGetSymbolAddress((void**)&pUL, g_ucat_lo);

    cudaFuncSetAttribute(gemm_fused, cudaFuncAttributeMaxDynamicSharedMemorySize,
                         SMEM_TOTAL);

    // 0) weight pack (interleaved) + x split
    prep_kernel<<<2048, 256>>>(W_iou, b_iou, U_iou, W_f, b_f, U_f);
    split_x_kernel<<<65534, 256>>>(x);

    // 1) big GEMM over all nodes; leaf rows fused-activate into buffers [0]
    {
        int M = BDIM * NNODE;  // 262136
        dim3 grid(8, (M + 127) / 128);
        gemm_fused<<<grid, 256, SMEM_TOTAL>>>(pXhi, pXlo, pWH, pWL,
                                              M, -1, 0, 0, 0, 0);
    }

    // 2) 14 levels: one fused GEMM+combine per level
    int p = 0;
    int lgn = 14;                          // log2(2n) for n = 8192
    for (int n = LLEAF / 2; n >= 1; n >>= 1, lgn--) {
        int pin = p, pout = 1 - p;
        const __nv_bfloat16* hhi = pHhi + (size_t)pin * 33554432;
        const __nv_bfloat16* hlo = pHlo + (size_t)pin * 33554432;

        int M = BDIM * 2 * n;              // all child rows
        dim3 g(8, (M + 127) / 128);
        gemm_fused<<<g, 256, SMEM_TOTAL>>>(hhi, hlo, pUH, pUL,
                                           M, lgn, 1, n, pin, pout);
        p = pout;
    }

    // 3) emit root h,c
    final_kernel<<<16, 256>>>(p, out);
}

// round 14
// speedup vs baseline: 2.0652x; 2.0652x over previous
#include <cuda_runtime.h>
#include <cuda_bf16.h>
#include <math.h>
#include <stdint.h>

// Problem constants
#define BDIM   8
#define LLEAF  16384
#define NNODE  32767      // 2*L - 1
#define DH     256
#define MAXN   16384
#define XELEMS 67106816ULL   // 8*32767*256

// ---------------------------------------------------------------------------
// Static device scratch
// ---------------------------------------------------------------------------
__device__ float g_pre[268427264];          // 8*32767*1024 : x@[Wiou|Wf]+bias
__device__ float g_gproj[134217728];        // 8*16384*1024 : h_child@[Uiou|Uf]
__device__ float g_c[2][33554432];          // ping-pong c (fp32)
__device__ __nv_bfloat16 g_hhi[2][33554432], g_hlo[2][33554432];  // split h
__device__ __nv_bfloat16 g_xhi[67106816], g_xlo[67106816];        // split x

// Packed transposed weights: rows = output col (1024), cols = k (256)
__device__ __nv_bfloat16 g_wcat_hi[262144], g_wcat_lo[262144];
__device__ __nv_bfloat16 g_ucat_hi[262144], g_ucat_lo[262144];
__device__ float g_bias[1024];

__device__ __forceinline__ float sigm(float v) { return 1.0f / (1.0f + expf(-v)); }

__device__ __forceinline__ uint32_t smem_u32(const void* p) {
    uint32_t a;
    asm("{ .reg .u64 t; cvta.to.shared.u64 t, %1; cvt.u32.u64 %0, t; }" : "=r"(a) : "l"(p));
    return a;
}

#define LDSM_X4(r0, r1, r2, r3, addr) \
    asm volatile("ldmatrix.sync.aligned.m8n8.x4.shared.b16 {%0,%1,%2,%3}, [%4];" \
                 : "=r"(r0), "=r"(r1), "=r"(r2), "=r"(r3) : "r"(addr))
#define LDSM_X2(r0, r1, addr) \
    asm volatile("ldmatrix.sync.aligned.m8n8.x2.shared.b16 {%0,%1}, [%2];" \
                 : "=r"(r0), "=r"(r1) : "r"(addr))
#define MMA_BF16(d, a0, a1, a2, a3, b0, b1) \
    asm volatile("mma.sync.aligned.m16n8k16.row.col.f32.bf16.bf16.f32 " \
                 "{%0,%1,%2,%3}, {%4,%5,%6,%7}, {%8,%9}, {%0,%1,%2,%3};" \
                 : "+f"((d)[0]), "+f"((d)[1]), "+f"((d)[2]), "+f"((d)[3]) \
                 : "r"(a0), "r"(a1), "r"(a2), "r"(a3), "r"(b0), "r"(b1))
#define CP_ASYNC(dst, src, sz) \
    asm volatile("cp.async.cg.shared.global [%0], [%1], 16, %2;" \
                 :: "r"(dst), "l"(src), "r"(sz))
#define CP_COMMIT() asm volatile("cp.async.commit_group;")
#define CP_WAIT1()  asm volatile("cp.async.wait_group 1;")
#define CP_WAIT0()  asm volatile("cp.async.wait_group 0;")

// ---------------------------------------------------------------------------
// Weight prep: pack [W_iou|W_f] and [U_iou|U_f] transposed, bf16 hi/lo split.
// ---------------------------------------------------------------------------
__global__ void prep_kernel(const float* __restrict__ W_iou,
                            const float* __restrict__ b_iou,
                            const float* __restrict__ U_iou,
                            const float* __restrict__ W_f,
                            const float* __restrict__ b_f,
                            const float* __restrict__ U_f) {
    int gid = blockIdx.x * blockDim.x + threadIdx.x;   // < 524288
    if (gid < 1024) g_bias[gid] = (gid < 768) ? b_iou[gid] : b_f[gid - 768];
    float v; __nv_bfloat16 *phi, *plo; int oi;
    if (gid < 262144) {            // Wcat^T
        int n = gid >> 8, k = gid & 255;
        v = (n < 768) ? W_iou[k * 768 + n] : W_f[k * 256 + (n - 768)];
        phi = g_wcat_hi; plo = g_wcat_lo; oi = gid;
    } else {                       // Ucat^T
        int t = gid - 262144; int n = t >> 8, k = t & 255;
        v = (n < 768) ? U_iou[k * 768 + n] : U_f[k * 256 + (n - 768)];
        phi = g_ucat_hi; plo = g_ucat_lo; oi = t;
    }
    __nv_bfloat16 hi = __float2bfloat16_rn(v);
    phi[oi] = hi;
    plo[oi] = __float2bfloat16_rn(v - __bfloat162float(hi));
}

// ---------------------------------------------------------------------------
// Split x (fp32) into bf16 hi/lo arrays.
// ---------------------------------------------------------------------------
__global__ void split_x_kernel(const float* __restrict__ x) {
    size_t base = ((size_t)blockIdx.x * 256 + threadIdx.x) * 4;
    if (base >= XELEMS) return;
    float4 v = *(const float4*)(x + base);
    __nv_bfloat162 h0 = __floats2bfloat162_rn(v.x, v.y);
    __nv_bfloat162 h1 = __floats2bfloat162_rn(v.z, v.w);
    __nv_bfloat162 l0 = __floats2bfloat162_rn(
        v.x - __bfloat162float(__low2bfloat16(h0)),
        v.y - __bfloat162float(__high2bfloat16(h0)));
    __nv_bfloat162 l1 = __floats2bfloat162_rn(
        v.z - __bfloat162float(__low2bfloat16(h1)),
        v.w - __bfloat162float(__high2bfloat16(h1)));
    *(uint2*)(g_xhi + base) = make_uint2(*(uint32_t*)&h0, *(uint32_t*)&h1);
    *(uint2*)(g_xlo + base) = make_uint2(*(uint32_t*)&l0, *(uint32_t*)&l1);
}

// ---------------------------------------------------------------------------
// HMMA bf16x3 GEMM, cp.async double-buffered. (R11 structure, +leafSkip)
//   C[M,1024] = A' @ Wt^T (+bias); K=256 in four 64-chunks, 2 stages.
//   Tile 128x128, 256 threads (2x4 warps), warp tile 64x32.
//   A row m: lgn<0 -> row=m; else row=(m>>lgn)*astride + (m & ((1<<lgn)-1)).
//   leafSkip: skip blocks whose rows are all leaf nodes and n0 >= 768
//   (leaf rows never consume the f-gate projection).
// ---------------------------------------------------------------------------
#define ARR_B   (128 * 144)          // 18432 bytes per array per stage
#define OFF_AHI 0
#define OFF_ALO ARR_B
#define OFF_BHI (2 * ARR_B)
#define OFF_BLO (3 * ARR_B)
#define STAGE_B (4 * ARR_B)          // 73728
#define SMEM_TOTAL (2 * STAGE_B)     // 147456

struct LoadCtx {
    const __nv_bfloat16 *sAhi[4], *sAlo[4], *sBhi[4], *sBlo[4];
    uint32_t szA[4], doff[4];
};

__device__ __forceinline__ void issue_stage(const LoadCtx& L, uint32_t sbase, int chunk) {
#pragma unroll
    for (int p = 0; p < 4; p++) {
        CP_ASYNC(sbase + OFF_AHI + L.doff[p], L.sAhi[p] + chunk * 64, L.szA[p]);
        CP_ASYNC(sbase + OFF_ALO + L.doff[p], L.sAlo[p] + chunk * 64, L.szA[p]);
        CP_ASYNC(sbase + OFF_BHI + L.doff[p], L.sBhi[p] + chunk * 64, 16u);
        CP_ASYNC(sbase + OFF_BLO + L.doff[p], L.sBlo[p] + chunk * 64, 16u);
    }
    CP_COMMIT();
}

__global__ __launch_bounds__(256, 1)
void gemm_hmma(const __nv_bfloat16* __restrict__ Ahi,
               const __nv_bfloat16* __restrict__ Alo,
               const __nv_bfloat16* __restrict__ Bhi,
               const __nv_bfloat16* __restrict__ Blo,
               const float* __restrict__ bias, float* __restrict__ C,
               int M, int lgn, int astride, int leafSkip) {
    const int m0 = blockIdx.y * 128;
    const int n0 = blockIdx.x * 128;

    // --- leaf x f-gate tile skip (big GEMM only) ---
    if (leafSkip && n0 >= 768) {
        int b0 = m0 / NNODE;
        int node0 = m0 - b0 * NNODE;
        int bLast = (m0 + 127) / NNODE;
        if (b0 == bLast && node0 >= LLEAF - 1) return;   // all rows are leaves
    }

    extern __shared__ char smem[];
    const uint32_t sb = smem_u32(smem);
    const int tid = threadIdx.x;
    const int wid = tid >> 5, lid = tid & 31;
    const int wm = wid >> 2, wn = wid & 3;

    float acc[4][4][4];
#pragma unroll
    for (int mi = 0; mi < 4; mi++)
#pragma unroll
        for (int ni = 0; ni < 4; ni++)
#pragma unroll
            for (int q = 0; q < 4; q++) acc[mi][ni][q] = 0.0f;

    // ---- loader context: 4 rows/thread, 16B segment each ----
    LoadCtx L;
    {
        const int rs = tid >> 3;
        const int seg = tid & 7;
#pragma unroll
        for (int p = 0; p < 4; p++) {
            int r = rs + 32 * p;
            L.doff[p] = (uint32_t)(r * 144 + seg * 16);
            int gm = m0 + r;
            size_t row = 0;
            if (gm < M) {
                if (lgn < 0) row = (size_t)gm;
                else {
                    int b = gm >> lgn;
                    int k = gm & ((1 << lgn) - 1);
                    row = (size_t)b * astride + k;
                }
                L.szA[p] = 16;
            } else L.szA[p] = 0;
            L.sAhi[p] = Ahi + row * 256 + seg * 8;
            L.sAlo[p] = Alo + row * 256 + seg * 8;
            int n = n0 + r;
            L.sBhi[p] = Bhi + (size_t)n * 256 + seg * 8;
            L.sBlo[p] = Blo + (size_t)n * 256 + seg * 8;
        }
    }

    const int arow = lid & 15, ahalf = lid >> 4;
    const int brow = lid & 7,  bhalf = (lid >> 3) & 1;

    issue_stage(L, sb, 0);
    issue_stage(L, sb + STAGE_B, 1);

#pragma unroll
    for (int c = 0; c < 4; c++) {
        if (c < 3) CP_WAIT1(); else CP_WAIT0();
        __syncthreads();
        const uint32_t sbase = sb + (uint32_t)(c & 1) * STAGE_B;

#pragma unroll
        for (int ks = 0; ks < 4; ks++) {
            uint32_t bh[4][2], bl[4][2];
#pragma unroll
            for (int ni = 0; ni < 4; ni++) {
                uint32_t ba = sbase + (uint32_t)((wn * 32 + ni * 8 + brow) * 144
                                                 + ks * 32 + bhalf * 16);
                LDSM_X2(bh[ni][0], bh[ni][1], ba + OFF_BHI);
                LDSM_X2(bl[ni][0], bl[ni][1], ba + OFF_BLO);
            }
#pragma unroll
            for (int mi = 0; mi < 4; mi++) {
                uint32_t aa = sbase + (uint32_t)((wm * 64 + mi * 16 + arow) * 144
                                                 + ks * 32 + ahalf * 16);
                uint32_t ah0, ah1, ah2, ah3, al0, al1, al2, al3;
                LDSM_X4(ah0, ah1, ah2, ah3, aa + OFF_AHI);
                LDSM_X4(al0, al1, al2, al3, aa + OFF_ALO);
#pragma unroll
                for (int ni = 0; ni < 4; ni++) {
                    MMA_BF16(acc[mi][ni], ah0, ah1, ah2, ah3, bh[ni][0], bh[ni][1]);
                    MMA_BF16(acc[mi][ni], ah0, ah1, ah2, ah3, bl[ni][0], bl[ni][1]);
                    MMA_BF16(acc[mi][ni], al0, al1, al2, al3, bh[ni][0], bh[ni][1]);
                }
            }
        }
        __syncthreads();
        if (c < 2) issue_stage(L, sbase, c + 2);
    }

    // ---- epilogue ----
    const int crow = lid >> 2;
    const int ccol = (lid & 3) * 2;
#pragma unroll
    for (int mi = 0; mi < 4; mi++) {
        const int gr0 = m0 + wm * 64 + mi * 16 + crow;
#pragma unroll
        for (int ni = 0; ni < 4; ni++) {
            const int gc = n0 + wn * 32 + ni * 8 + ccol;
            float b0 = 0.f, b1 = 0.f;
            if (bias) { b0 = bias[gc]; b1 = bias[gc + 1]; }
            if (gr0 < M) {
                float2 v = make_float2(acc[mi][ni][0] + b0, acc[mi][ni][1] + b1);
                *(float2*)(C + (size_t)gr0 * 1024 + gc) = v;
            }
            if (gr0 + 8 < M) {
                float2 v = make_float2(acc[mi][ni][2] + b0, acc[mi][ni][3] + b1);
                *(float2*)(C + (size_t)(gr0 + 8) * 1024 + gc) = v;
            }
        }
    }
}

// ---------------------------------------------------------------------------
// Leaf activation -> ping buffer 0 (float4 vectorized: 4 channels per thread)
// ---------------------------------------------------------------------------
__global__ void leaf_kernel() {
    size_t gid = (size_t)blockIdx.x * blockDim.x + threadIdx.x;  // B*L*64
    int j4 = (int)(gid & 63) * 4;
    size_t m = gid >> 6;            // b*L + k
    int b = (int)(m >> 14);
    int k = (int)(m & 16383);
    size_t prerow = ((size_t)b * NNODE + (LLEAF - 1) + k) * 1024;
    float4 iv = *(const float4*)(g_pre + prerow + j4);
    float4 ov = *(const float4*)(g_pre + prerow + 256 + j4);
    float4 uv = *(const float4*)(g_pre + prerow + 512 + j4);
    float4 cv, hv;
    cv.x = sigm(iv.x) * tanhf(uv.x);  hv.x = sigm(ov.x) * tanhf(cv.x);
    cv.y = sigm(iv.y) * tanhf(uv.y);  hv.y = sigm(ov.y) * tanhf(cv.y);
    cv.z = sigm(iv.z) * tanhf(uv.z);  hv.z = sigm(ov.z) * tanhf(cv.z);
    cv.w = sigm(iv.w) * tanhf(uv.w);  hv.w = sigm(ov.w) * tanhf(cv.w);
    size_t idx = ((size_t)b * MAXN + k) * 256 + j4;
    *(float4*)(g_c[0] + idx) = cv;
    __nv_bfloat162 h0 = __floats2bfloat162_rn(hv.x, hv.y);
    __nv_bfloat162 h1 = __floats2bfloat162_rn(hv.z, hv.w);
    __nv_bfloat162 l0 = __floats2bfloat162_rn(
        hv.x - __bfloat162float(__low2bfloat16(h0)),
        hv.y - __bfloat162float(__high2bfloat16(h0)));
    __nv_bfloat162 l1 = __floats2bfloat162_rn(
        hv.z - __bfloat162float(__low2bfloat16(h1)),
        hv.w - __bfloat162float(__high2bfloat16(h1)));
    *(uint2*)(g_hhi[0] + idx) = make_uint2(*(uint32_t*)&h0, *(uint32_t*)&h1);
    *(uint2*)(g_hlo[0] + idx) = make_uint2(*(uint32_t*)&l0, *(uint32_t*)&l1);
}

// ---------------------------------------------------------------------------
// Per-level combine (float4 vectorized: 4 channels per thread).
// gproj rows = per-child [iou(768) | f(256)] projections.
// ---------------------------------------------------------------------------
__global__ void combine_kernel(int n, int pin, int pout) {
    size_t gid = (size_t)blockIdx.x * blockDim.x + threadIdx.x;
    size_t total = (size_t)BDIM * n * 64;
    if (gid >= total) return;
    int j4 = (int)(gid & 63) * 4;
    size_t m = gid >> 6;            // b*n + k
    int b = (int)(m / (unsigned)n);
    int k = (int)(m - (size_t)b * n);
    int node = (n - 1) + k;

    size_t prow = ((size_t)b * NNODE + node) * 1024;
    size_t g0 = ((size_t)b * (2 * n) + 2 * k) * 1024;

    float4 pi = *(const float4*)(g_pre + prow + j4);
    float4 po = *(const float4*)(g_pre + prow + 256 + j4);
    float4 pu = *(const float4*)(g_pre + prow + 512 + j4);
    float4 pf = *(const float4*)(g_pre + prow + 768 + j4);

    float4 ai0 = *(const float4*)(g_gproj + g0 + j4);
    float4 ao0 = *(const float4*)(g_gproj + g0 + 256 + j4);
    float4 au0 = *(const float4*)(g_gproj + g0 + 512 + j4);
    float4 af0 = *(const float4*)(g_gproj + g0 + 768 + j4);
    float4 ai1 = *(const float4*)(g_gproj + g0 + 1024 + j4);
    float4 ao1 = *(const float4*)(g_gproj + g0 + 1280 + j4);
    float4 au1 = *(const float4*)(g_gproj + g0 + 1536 + j4);
    float4 af1 = *(const float4*)(g_gproj + g0 + 1792 + j4);

    size_t cbase = ((size_t)b * MAXN + 2 * k) * 256 + j4;
    float4 c0 = *(const float4*)(g_c[pin] + cbase);
    float4 c1 = *(const float4*)(g_c[pin] + cbase + 256);

    float4 cn, hn;
#define CHAN(f) { \
    float iv = pi.f + ai0.f + ai1.f; \
    float ov = po.f + ao0.f + ao1.f; \
    float uv = pu.f + au0.f + au1.f; \
    float f0 = sigm(pf.f + af0.f); \
    float f1 = sigm(pf.f + af1.f); \
    cn.f = sigm(iv) * tanhf(uv) + f0 * c0.f + f1 * c1.f; \
    hn.f = sigm(ov) * tanhf(cn.f); }
    CHAN(x) CHAN(y) CHAN(z) CHAN(w)
#undef CHAN

    size_t o = ((size_t)b * MAXN + k) * 256 + j4;
    *(float4*)(g_c[pout] + o) = cn;
    __nv_bfloat162 h0 = __floats2bfloat162_rn(hn.x, hn.y);
    __nv_bfloat162 h1 = __floats2bfloat162_rn(hn.z, hn.w);
    __nv_bfloat162 l0 = __floats2bfloat162_rn(
        hn.x - __bfloat162float(__low2bfloat16(h0)),
        hn.y - __bfloat162float(__high2bfloat16(h0)));
    __nv_bfloat162 l1 = __floats2bfloat162_rn(
        hn.z - __bfloat162float(__low2bfloat16(h1)),
        hn.w - __bfloat162float(__high2bfloat16(h1)));
    *(uint2*)(g_hhi[pout] + o) = make_uint2(*(uint32_t*)&h0, *(uint32_t*)&h1);
    *(uint2*)(g_hlo[pout] + o) = make_uint2(*(uint32_t*)&l0, *(uint32_t*)&l1);
}

// ---------------------------------------------------------------------------
__global__ void final_kernel(int p, float* __restrict__ out) {
    int gid = blockIdx.x * blockDim.x + threadIdx.x;
    if (gid >= BDIM * 512) return;
    int b = gid >> 9;
    int j = gid & 511;
    size_t base = ((size_t)b * MAXN) * 256;
    if (j < 256) {
        out[gid] = __bfloat162float(g_hhi[p][base + j])
                 + __bfloat162float(g_hlo[p][base + j]);
    } else {
        out[gid] = g_c[p][base + j - 256];
    }
}

// ---------------------------------------------------------------------------
extern "C" void kernel_launch(void* const* d_in, const int* in_sizes, int n_in,
                              void* d_out, int out_size) {
    const float* x     = (const float*)d_in[0];
    const float* W_iou = (const float*)d_in[1];
    const float* b_iou = (const float*)d_in[2];
    const float* U_iou = (const float*)d_in[3];
    const float* W_f   = (const float*)d_in[4];
    const float* b_f   = (const float*)d_in[5];
    const float* U_f   = (const float*)d_in[6];
    float* out = (float*)d_out;

    float *pPre, *pGproj, *pBias;
    cudaGetSymbolAddress((void**)&pPre, g_pre);
    cudaGetSymbolAddress((void**)&pGproj, g_gproj);
    cudaGetSymbolAddress((void**)&pBias, g_bias);
    __nv_bfloat16 *pXhi, *pXlo, *pHhi, *pHlo, *pWH, *pWL, *pUH, *pUL;
    cudaGetSymbolAddress((void**)&pXhi, g_xhi);
    cudaGetSymbolAddress((void**)&pXlo, g_xlo);
    cudaGetSymbolAddress((void**)&pHhi, g_hhi);
    cudaGetSymbolAddress((void**)&pHlo, g_hlo);
    cudaGetSymbolAddress((void**)&pWH, g_wcat_hi);
    cudaGetSymbolAddress((void**)&pWL, g_wcat_lo);
    cudaGetSymbolAddress((void**)&pUH, g_ucat_hi);
    cudaGetSymbolAddress((void**)&pUL, g_ucat_lo);

    cudaFuncSetAttribute(gemm_hmma, cudaFuncAttributeMaxDynamicSharedMemorySize,
                         SMEM_TOTAL);

    // 0) weight pack + x split
    prep_kernel<<<2048, 256>>>(W_iou, b_iou, U_iou, W_f, b_f, U_f);
    split_x_kernel<<<65534, 256>>>(x);

    // 1) pre = x @ [Wiou|Wf] + bias, all nodes  [B*NNODE, 1024]
    //    (leaf x f-gate tiles skipped inside the kernel)
    {
        int M = BDIM * NNODE;  // 262136
        dim3 grid(8, (M + 127) / 128);
        gemm_hmma<<<grid, 256, SMEM_TOTAL>>>(pXhi, pXlo, pWH, pWL, pBias, pPre,
                                             M, -1, 0, 1);
    }

    // 2) leaf activations -> ping buffer 0
    leaf_kernel<<<(BDIM * LLEAF * 64) / 256, 256>>>();

    // 3) 14 levels: one GEMM (all children x Ucat) + combine per level
    int p = 0;
    int lgn = 14;                         // log2(2n) for n = 8192
    for (int n = LLEAF / 2; n >= 1; n >>= 1, lgn--) {
        int pin = p, pout = 1 - p;
        const __nv_bfloat16* hhi = pHhi + (size_t)pin * 33554432;
        const __nv_bfloat16* hlo = pHlo + (size_t)pin * 33554432;

        int M = BDIM * 2 * n;             // all child rows
        dim3 g(8, (M + 127) / 128);
        gemm_hmma<<<g, 256, SMEM_TOTAL>>>(hhi, hlo, pUH, pUL, nullptr, pGproj,
                                          M, lgn, MAXN, 0);

        size_t tot = (size_t)BDIM * n * 64;
        combine_kernel<<<(unsigned)((tot + 255) / 256), 256>>>(n, pin, pout);
        p = pout;
    }

    // 4) emit root h,c
    final_kernel<<<16, 256>>>(p, out);
}

// round 16
// speedup vs baseline: 2.1822x; 1.0566x over previous
#include <cuda_runtime.h>
#include <cuda_bf16.h>
#include <math.h>
#include <stdint.h>

// Problem constants
#define BDIM   8
#define LLEAF  16384
#define NNODE  32767      // 2*L - 1
#define DH     256
#define MAXN   16384
#define XELEMS 67106816ULL   // 8*32767*256

// ---------------------------------------------------------------------------
// Static device scratch
// ---------------------------------------------------------------------------
__device__ float g_pre[268427264];          // 8*32767*1024 : x@[Wiou|Wf]+bias
__device__ float g_gproj[134217728];        // 8*16384*1024 : h_child@[Uiou|Uf]
__device__ float g_c[2][33554432];          // ping-pong c (fp32)
__device__ __nv_bfloat16 g_hhi[2][33554432], g_hlo[2][33554432];  // split h
__device__ __nv_bfloat16 g_xhi[67106816], g_xlo[67106816];        // split x

// Packed transposed weights: rows = output col (1024), cols = k (256)
__device__ __nv_bfloat16 g_wcat_hi[262144], g_wcat_lo[262144];
__device__ __nv_bfloat16 g_ucat_hi[262144], g_ucat_lo[262144];
__device__ float g_bias[1024];

__device__ __forceinline__ float sigm(float v) { return 1.0f / (1.0f + expf(-v)); }

__device__ __forceinline__ uint32_t smem_u32(const void* p) {
    uint32_t a;
    asm("{ .reg .u64 t; cvta.to.shared.u64 t, %1; cvt.u32.u64 %0, t; }" : "=r"(a) : "l"(p));
    return a;
}

#define LDSM_X4(r0, r1, r2, r3, addr) \
    asm volatile("ldmatrix.sync.aligned.m8n8.x4.shared.b16 {%0,%1,%2,%3}, [%4];" \
                 : "=r"(r0), "=r"(r1), "=r"(r2), "=r"(r3) : "r"(addr))
#define LDSM_X2(r0, r1, addr) \
    asm volatile("ldmatrix.sync.aligned.m8n8.x2.shared.b16 {%0,%1}, [%2];" \
                 : "=r"(r0), "=r"(r1) : "r"(addr))
#define MMA_BF16(d, a0, a1, a2, a3, b0, b1) \
    asm volatile("mma.sync.aligned.m16n8k16.row.col.f32.bf16.bf16.f32 " \
                 "{%0,%1,%2,%3}, {%4,%5,%6,%7}, {%8,%9}, {%0,%1,%2,%3};" \
                 : "+f"((d)[0]), "+f"((d)[1]), "+f"((d)[2]), "+f"((d)[3]) \
                 : "r"(a0), "r"(a1), "r"(a2), "r"(a3), "r"(b0), "r"(b1))
#define CP_ASYNC(dst, src, sz) \
    asm volatile("cp.async.cg.shared.global [%0], [%1], 16, %2;" \
                 :: "r"(dst), "l"(src), "r"(sz))
#define CP_COMMIT() asm volatile("cp.async.commit_group;")
#define CP_WAIT1()  asm volatile("cp.async.wait_group 1;")
#define CP_WAIT0()  asm volatile("cp.async.wait_group 0;")

// ---------------------------------------------------------------------------
// Weight prep: pack [W_iou|W_f] and [U_iou|U_f] transposed, bf16 hi/lo split.
// ---------------------------------------------------------------------------
__global__ void prep_kernel(const float* __restrict__ W_iou,
                            const float* __restrict__ b_iou,
                            const float* __restrict__ U_iou,
                            const float* __restrict__ W_f,
                            const float* __restrict__ b_f,
                            const float* __restrict__ U_f) {
    int gid = blockIdx.x * blockDim.x + threadIdx.x;   // < 524288
    if (gid < 1024) g_bias[gid] = (gid < 768) ? b_iou[gid] : b_f[gid - 768];
    float v; __nv_bfloat16 *phi, *plo; int oi;
    if (gid < 262144) {            // Wcat^T
        int n = gid >> 8, k = gid & 255;
        v = (n < 768) ? W_iou[k * 768 + n] : W_f[k * 256 + (n - 768)];
        phi = g_wcat_hi; plo = g_wcat_lo; oi = gid;
    } else {                       // Ucat^T
        int t = gid - 262144; int n = t >> 8, k = t & 255;
        v = (n < 768) ? U_iou[k * 768 + n] : U_f[k * 256 + (n - 768)];
        phi = g_ucat_hi; plo = g_ucat_lo; oi = t;
    }
    __nv_bfloat16 hi = __float2bfloat16_rn(v);
    phi[oi] = hi;
    plo[oi] = __float2bfloat16_rn(v - __bfloat162float(hi));
}

// ---------------------------------------------------------------------------
// Split x (fp32) into bf16 hi/lo arrays.
// ---------------------------------------------------------------------------
__global__ void split_x_kernel(const float* __restrict__ x) {
    size_t base = ((size_t)blockIdx.x * 256 + threadIdx.x) * 4;
    if (base >= XELEMS) return;
    float4 v = *(const float4*)(x + base);
    __nv_bfloat162 h0 = __floats2bfloat162_rn(v.x, v.y);
    __nv_bfloat162 h1 = __floats2bfloat162_rn(v.z, v.w);
    __nv_bfloat162 l0 = __floats2bfloat162_rn(
        v.x - __bfloat162float(__low2bfloat16(h0)),
        v.y - __bfloat162float(__high2bfloat16(h0)));
    __nv_bfloat162 l1 = __floats2bfloat162_rn(
        v.z - __bfloat162float(__low2bfloat16(h1)),
        v.w - __bfloat162float(__high2bfloat16(h1)));
    *(uint2*)(g_xhi + base) = make_uint2(*(uint32_t*)&h0, *(uint32_t*)&h1);
    *(uint2*)(g_xlo + base) = make_uint2(*(uint32_t*)&l0, *(uint32_t*)&l1);
}

// ---------------------------------------------------------------------------
// HMMA bf16x3 GEMM, cp.async double-buffered, 2 CTAs/SM.
//   C[M,1024] = A' @ Wt^T (+bias); K=256 in eight 32-chunks, 2 stages.
//   Tile 128x128, 256 threads (2x4 warps), warp tile 64x32.
//   Stage rows are 80B (64B data + 16B pad) -> conflict-free ldmatrix,
//   stage = 40960B, two stages = 81920B  => 2 CTAs per SM.
//   A row m: lgn<0 -> row=m; else row=(m>>lgn)*astride + (m & ((1<<lgn)-1)).
//   leafSkip: skip blocks whose rows are all leaf nodes and n0 >= 768.
// ---------------------------------------------------------------------------
#define ROWB    80                   // bytes per smem row (32 bf16 + pad)
#define ARR_B   (128 * ROWB)         // 10240 bytes per array per stage
#define OFF_AHI 0
#define OFF_ALO ARR_B
#define OFF_BHI (2 * ARR_B)
#define OFF_BLO (3 * ARR_B)
#define STAGE_B (4 * ARR_B)          // 40960
#define SMEM_TOTAL (2 * STAGE_B)     // 81920

struct LoadCtx {
    const __nv_bfloat16 *sAhi[2], *sAlo[2], *sBhi[2], *sBlo[2];
    uint32_t szA[2], doff[2];
};

__device__ __forceinline__ void issue_stage(const LoadCtx& L, uint32_t sbase, int chunk) {
#pragma unroll
    for (int p = 0; p < 2; p++) {
        CP_ASYNC(sbase + OFF_AHI + L.doff[p], L.sAhi[p] + chunk * 32, L.szA[p]);
        CP_ASYNC(sbase + OFF_ALO + L.doff[p], L.sAlo[p] + chunk * 32, L.szA[p]);
        CP_ASYNC(sbase + OFF_BHI + L.doff[p], L.sBhi[p] + chunk * 32, 16u);
        CP_ASYNC(sbase + OFF_BLO + L.doff[p], L.sBlo[p] + chunk * 32, 16u);
    }
    CP_COMMIT();
}

__global__ __launch_bounds__(256, 2)
void gemm_hmma(const __nv_bfloat16* __restrict__ Ahi,
               const __nv_bfloat16* __restrict__ Alo,
               const __nv_bfloat16* __restrict__ Bhi,
               const __nv_bfloat16* __restrict__ Blo,
               const float* __restrict__ bias, float* __restrict__ C,
               int M, int lgn, int astride, int leafSkip) {
    const int m0 = blockIdx.y * 128;
    const int n0 = blockIdx.x * 128;

    // --- leaf x f-gate tile skip (big GEMM only) ---
    if (leafSkip && n0 >= 768) {
        int b0 = m0 / NNODE;
        int node0 = m0 - b0 * NNODE;
        int bLast = (m0 + 127) / NNODE;
        if (b0 == bLast && node0 >= LLEAF - 1) return;   // all rows are leaves
    }

    extern __shared__ char smem[];
    const uint32_t sb = smem_u32(smem);
    const int tid = threadIdx.x;
    const int wid = tid >> 5, lid = tid & 31;
    const int wm = wid >> 2, wn = wid & 3;

    float acc[4][4][4];
#pragma unroll
    for (int mi = 0; mi < 4; mi++)
#pragma unroll
        for (int ni = 0; ni < 4; ni++)
#pragma unroll
            for (int q = 0; q < 4; q++) acc[mi][ni][q] = 0.0f;

    // ---- loader context: 2 rows/thread, 16B segment each (4 threads/row) ----
    LoadCtx L;
    {
        const int rs = tid >> 2;          // 0..63
        const int seg = tid & 3;          // 0..3
#pragma unroll
        for (int p = 0; p < 2; p++) {
            int r = rs + 64 * p;
            L.doff[p] = (uint32_t)(r * ROWB + seg * 16);
            int gm = m0 + r;
            size_t row = 0;
            if (gm < M) {
                if (lgn < 0) row = (size_t)gm;
                else {
                    int b = gm >> lgn;
                    int k = gm & ((1 << lgn) - 1);
                    row = (size_t)b * astride + k;
                }
                L.szA[p] = 16;
            } else L.szA[p] = 0;
            L.sAhi[p] = Ahi + row * 256 + seg * 8;
            L.sAlo[p] = Alo + row * 256 + seg * 8;
            int n = n0 + r;
            L.sBhi[p] = Bhi + (size_t)n * 256 + seg * 8;
            L.sBlo[p] = Blo + (size_t)n * 256 + seg * 8;
        }
    }

    const int arow = lid & 15, ahalf = lid >> 4;
    const int brow = lid & 7,  bhalf = (lid >> 3) & 1;

    issue_stage(L, sb, 0);
    issue_stage(L, sb + STAGE_B, 1);

#pragma unroll
    for (int c = 0; c < 8; c++) {
        if (c < 7) CP_WAIT1(); else CP_WAIT0();
        __syncthreads();
        const uint32_t sbase = sb + (uint32_t)(c & 1) * STAGE_B;

#pragma unroll
        for (int ks = 0; ks < 2; ks++) {
            uint32_t bh[4][2], bl[4][2];
#pragma unroll
            for (int ni = 0; ni < 4; ni++) {
                uint32_t ba = sbase + (uint32_t)((wn * 32 + ni * 8 + brow) * ROWB
                                                 + ks * 32 + bhalf * 16);
                LDSM_X2(bh[ni][0], bh[ni][1], ba + OFF_BHI);
                LDSM_X2(bl[ni][0], bl[ni][1], ba + OFF_BLO);
            }
#pragma unroll
            for (int mi = 0; mi < 4; mi++) {
                uint32_t aa = sbase + (uint32_t)((wm * 64 + mi * 16 + arow) * ROWB
                                                 + ks * 32 + ahalf * 16);
                uint32_t ah0, ah1, ah2, ah3, al0, al1, al2, al3;
                LDSM_X4(ah0, ah1, ah2, ah3, aa + OFF_AHI);
                LDSM_X4(al0, al1, al2, al3, aa + OFF_ALO);
#pragma unroll
                for (int ni = 0; ni < 4; ni++) {
                    MMA_BF16(acc[mi][ni], ah0, ah1, ah2, ah3, bh[ni][0], bh[ni][1]);
                    MMA_BF16(acc[mi][ni], ah0, ah1, ah2, ah3, bl[ni][0], bl[ni][1]);
                    MMA_BF16(acc[mi][ni], al0, al1, al2, al3, bh[ni][0], bh[ni][1]);
                }
            }
        }
        __syncthreads();
        if (c < 6) issue_stage(L, sbase, c + 2);
    }

    // ---- epilogue ----
    const int crow = lid >> 2;
    const int ccol = (lid & 3) * 2;
#pragma unroll
    for (int mi = 0; mi < 4; mi++) {
        const int gr0 = m0 + wm * 64 + mi * 16 + crow;
#pragma unroll
        for (int ni = 0; ni < 4; ni++) {
            const int gc = n0 + wn * 32 + ni * 8 + ccol;
            float b0 = 0.f, b1 = 0.f;
            if (bias) { b0 = bias[gc]; b1 = bias[gc + 1]; }
            if (gr0 < M) {
                float2 v = make_float2(acc[mi][ni][0] + b0, acc[mi][ni][1] + b1);
                *(float2*)(C + (size_t)gr0 * 1024 + gc) = v;
            }
            if (gr0 + 8 < M) {
                float2 v = make_float2(acc[mi][ni][2] + b0, acc[mi][ni][3] + b1);
                *(float2*)(C + (size_t)(gr0 + 8) * 1024 + gc) = v;
            }
        }
    }
}

// ---------------------------------------------------------------------------
// Leaf activation -> ping buffer 0 (float4 vectorized: 4 channels per thread)
// ---------------------------------------------------------------------------
__global__ void leaf_kernel() {
    size_t gid = (size_t)blockIdx.x * blockDim.x + threadIdx.x;  // B*L*64
    int j4 = (int)(gid & 63) * 4;
    size_t m = gid >> 6;            // b*L + k
    int b = (int)(m >> 14);
    int k = (int)(m & 16383);
    size_t prerow = ((size_t)b * NNODE + (LLEAF - 1) + k) * 1024;
    float4 iv = *(const float4*)(g_pre + prerow + j4);
    float4 ov = *(const float4*)(g_pre + prerow + 256 + j4);
    float4 uv = *(const float4*)(g_pre + prerow + 512 + j4);
    float4 cv, hv;
    cv.x = sigm(iv.x) * tanhf(uv.x);  hv.x = sigm(ov.x) * tanhf(cv.x);
    cv.y = sigm(iv.y) * tanhf(uv.y);  hv.y = sigm(ov.y) * tanhf(cv.y);
    cv.z = sigm(iv.z) * tanhf(uv.z);  hv.z = sigm(ov.z) * tanhf(cv.z);
    cv.w = sigm(iv.w) * tanhf(uv.w);  hv.w = sigm(ov.w) * tanhf(cv.w);
    size_t idx = ((size_t)b * MAXN + k) * 256 + j4;
    *(float4*)(g_c[0] + idx) = cv;
    __nv_bfloat162 h0 = __floats2bfloat162_rn(hv.x, hv.y);
    __nv_bfloat162 h1 = __floats2bfloat162_rn(hv.z, hv.w);
    __nv_bfloat162 l0 = __floats2bfloat162_rn(
        hv.x - __bfloat162float(__low2bfloat16(h0)),
        hv.y - __bfloat162float(__high2bfloat16(h0)));
    __nv_bfloat162 l1 = __floats2bfloat162_rn(
        hv.z - __bfloat162float(__low2bfloat16(h1)),
        hv.w - __bfloat162float(__high2bfloat16(h1)));
    *(uint2*)(g_hhi[0] + idx) = make_uint2(*(uint32_t*)&h0, *(uint32_t*)&h1);
    *(uint2*)(g_hlo[0] + idx) = make_uint2(*(uint32_t*)&l0, *(uint32_t*)&l1);
}

// ---------------------------------------------------------------------------
// Per-level combine (float4 vectorized: 4 channels per thread).
// gproj rows = per-child [iou(768) | f(256)] projections.
// ---------------------------------------------------------------------------
__global__ void combine_kernel(int n, int pin, int pout) {
    size_t gid = (size_t)blockIdx.x * blockDim.x + threadIdx.x;
    size_t total = (size_t)BDIM * n * 64;
    if (gid >= total) return;
    int j4 = (int)(gid & 63) * 4;
    size_t m = gid >> 6;            // b*n + k
    int b = (int)(m / (unsigned)n);
    int k = (int)(m - (size_t)b * n);
    int node = (n - 1) + k;

    size_t prow = ((size_t)b * NNODE + node) * 1024;
    size_t g0 = ((size_t)b * (2 * n) + 2 * k) * 1024;

    float4 pi = *(const float4*)(g_pre + prow + j4);
    float4 po = *(const float4*)(g_pre + prow + 256 + j4);
    float4 pu = *(const float4*)(g_pre + prow + 512 + j4);
    float4 pf = *(const float4*)(g_pre + prow + 768 + j4);

    float4 ai0 = *(const float4*)(g_gproj + g0 + j4);
    float4 ao0 = *(const float4*)(g_gproj + g0 + 256 + j4);
    float4 au0 = *(const float4*)(g_gproj + g0 + 512 + j4);
    float4 af0 = *(const float4*)(g_gproj + g0 + 768 + j4);
    float4 ai1 = *(const float4*)(g_gproj + g0 + 1024 + j4);
    float4 ao1 = *(const float4*)(g_gproj + g0 + 1280 + j4);
    float4 au1 = *(const float4*)(g_gproj + g0 + 1536 + j4);
    float4 af1 = *(const float4*)(g_gproj + g0 + 1792 + j4);

    size_t cbase = ((size_t)b * MAXN + 2 * k) * 256 + j4;
    float4 c0 = *(const float4*)(g_c[pin] + cbase);
    float4 c1 = *(const float4*)(g_c[pin] + cbase + 256);

    float4 cn, hn;
#define CHAN(f) { \
    float iv = pi.f + ai0.f + ai1.f; \
    float ov = po.f + ao0.f + ao1.f; \
    float uv = pu.f + au0.f + au1.f; \
    float f0 = sigm(pf.f + af0.f); \
    float f1 = sigm(pf.f + af1.f); \
    cn.f = sigm(iv) * tanhf(uv) + f0 * c0.f + f1 * c1.f; \
    hn.f = sigm(ov) * tanhf(cn.f); }
    CHAN(x) CHAN(y) CHAN(z) CHAN(w)
#undef CHAN

    size_t o = ((size_t)b * MAXN + k) * 256 + j4;
    *(float4*)(g_c[pout] + o) = cn;
    __nv_bfloat162 h0 = __floats2bfloat162_rn(hn.x, hn.y);
    __nv_bfloat162 h1 = __floats2bfloat162_rn(hn.z, hn.w);
    __nv_bfloat162 l0 = __floats2bfloat162_rn(
        hn.x - __bfloat162float(__low2bfloat16(h0)),
        hn.y - __bfloat162float(__high2bfloat16(h0)));
    __nv_bfloat162 l1 = __floats2bfloat162_rn(
        hn.z - __bfloat162float(__low2bfloat16(h1)),
        hn.w - __bfloat162float(__high2bfloat16(h1)));
    *(uint2*)(g_hhi[pout] + o) = make_uint2(*(uint32_t*)&h0, *(uint32_t*)&h1);
    *(uint2*)(g_hlo[pout] + o) = make_uint2(*(uint32_t*)&l0, *(uint32_t*)&l1);
}

// ---------------------------------------------------------------------------
__global__ void final_kernel(int p, float* __restrict__ out) {
    int gid = blockIdx.x * blockDim.x + threadIdx.x;
    if (gid >= BDIM * 512) return;
    int b = gid >> 9;
    int j = gid & 511;
    size_t base = ((size_t)b * MAXN) * 256;
    if (j < 256) {
        out[gid] = __bfloat162float(g_hhi[p][base + j])
                 + __bfloat162float(g_hlo[p][base + j]);
    } else {
        out[gid] = g_c[p][base + j - 256];
    }
}

// ---------------------------------------------------------------------------
extern "C" void kernel_launch(void* const* d_in, const int* in_sizes, int n_in,
                              void* d_out, int out_size) {
    const float* x     = (const float*)d_in[0];
    const float* W_iou = (const float*)d_in[1];
    const float* b_iou = (const float*)d_in[2];
    const float* U_iou = (const float*)d_in[3];
    const float* W_f   = (const float*)d_in[4];
    const float* b_f   = (const float*)d_in[5];
    const float* U_f   = (const float*)d_in[6];
    float* out = (float*)d_out;

    float *pPre, *pGproj, *pBias;
    cudaGetSymbolAddress((void**)&pPre, g_pre);
    cudaGetSymbolAddress((void**)&pGproj, g_gproj);
    cudaGetSymbolAddress((void**)&pBias, g_bias);
    __nv_bfloat16 *pXhi, *pXlo, *pHhi, *pHlo, *pWH, *pWL, *pUH, *pUL;
    cudaGetSymbolAddress((void**)&pXhi, g_xhi);
    cudaGetSymbolAddress((void**)&pXlo, g_xlo);
    cudaGetSymbolAddress((void**)&pHhi, g_hhi);
    cudaGetSymbolAddress((void**)&pHlo, g_hlo);
    cudaGetSymbolAddress((void**)&pWH, g_wcat_hi);
    cudaGetSymbolAddress((void**)&pWL, g_wcat_lo);
    cudaGetSymbolAddress((void**)&pUH, g_ucat_hi);
    cudaGetSymbolAddress((void**)&pUL, g_ucat_lo);

    cudaFuncSetAttribute(gemm_hmma, cudaFuncAttributeMaxDynamicSharedMemorySize,
                         SMEM_TOTAL);

    // 0) weight pack + x split
    prep_kernel<<<2048, 256>>>(W_iou, b_iou, U_iou, W_f, b_f, U_f);
    split_x_kernel<<<65534, 256>>>(x);

    // 1) pre = x @ [Wiou|Wf] + bias, all nodes  [B*NNODE, 1024]
    //    (leaf x f-gate tiles skipped inside the kernel)
    {
        int M = BDIM * NNODE;  // 262136
        dim3 grid(8, (M + 127) / 128);
        gemm_hmma<<<grid, 256, SMEM_TOTAL>>>(pXhi, pXlo, pWH, pWL, pBias, pPre,
                                             M, -1, 0, 1);
    }

    // 2) leaf activations -> ping buffer 0
    leaf_kernel<<<(BDIM * LLEAF * 64) / 256, 256>>>();

    // 3) 14 levels: one GEMM (all children x Ucat) + combine per level
    int p = 0;
    int lgn = 14;                         // log2(2n) for n = 8192
    for (int n = LLEAF / 2; n >= 1; n >>= 1, lgn--) {
        int pin = p, pout = 1 - p;
        const __nv_bfloat16* hhi = pHhi + (size_t)pin * 33554432;
        const __nv_bfloat16* hlo = pHlo + (size_t)pin * 33554432;

        int M = BDIM * 2 * n;             // all child rows
        dim3 g(8, (M + 127) / 128);
        gemm_hmma<<<g, 256, SMEM_TOTAL>>>(hhi, hlo, pUH, pUL, nullptr, pGproj,
                                          M, lgn, MAXN, 0);

        size_t tot = (size_t)BDIM * n * 64;
        combine_kernel<<<(unsigned)((tot + 255) / 256), 256>>>(n, pin, pout);
        p = pout;
    }

    // 4) emit root h,c
    final_kernel<<<16, 256>>>(p, out);
}